// round 11
// baseline (speedup 1.0000x reference)
#include <cuda_runtime.h>
#include <cuda_fp16.h>
#include <cstdint>
#include <cstddef>

#define DEV __device__ __forceinline__

static constexpr int Bn = 8192;   // batch rows
static constexpr int Dd = 2048;   // model dim (K of GEMMs, N of V GEMM)
static constexpr int Ff = 1024;   // feature dim (N of Q/K GEMMs)

// ---------------- scratch (device globals: allocation-free) ----------------
__device__ __half g_Qh [(size_t)Bn * Dd];   // 32 MB
__device__ __half g_Kh [(size_t)Bn * Dd];   // 32 MB
__device__ __half g_Vh [(size_t)Bn * Dd];   // 32 MB
__device__ __half g_WqT[(size_t)Ff * Dd];   // [F][D] 4 MB
__device__ __half g_WkT[(size_t)Ff * Dd];   // [F][D] 4 MB
__device__ __half g_WvT[(size_t)Dd * Dd];   // [D][D] 8 MB
__device__ float g_sQ[Bn];
__device__ float g_sK[Bn];
__device__ float g_qk[Bn];

// ---------------- helpers ----------------
DEV uint32_t smem_u32(const void* p) {
  uint32_t a;
  asm("{ .reg .u64 t; cvta.to.shared.u64 t, %1; cvt.u32.u64 %0, t; }" : "=r"(a) : "l"(p));
  return a;
}
DEV void cp16(uint32_t dst, const void* src) {
  asm volatile("cp.async.cg.shared.global [%0], [%1], 16;" :: "r"(dst), "l"(src));
}
DEV void cp_commit() { asm volatile("cp.async.commit_group;" ::: "memory"); }
DEV void cp_wait0()  { asm volatile("cp.async.wait_group 0;" ::: "memory"); }
DEV void cp_wait1()  { asm volatile("cp.async.wait_group 1;" ::: "memory"); }

// mma m16n8k16 fp16 (fp32 acc)
DEV void mma16(float c[4], const uint32_t a[4], const uint32_t b[2]) {
  asm volatile(
    "mma.sync.aligned.m16n8k16.row.col.f32.f16.f16.f32 "
    "{%0,%1,%2,%3}, {%4,%5,%6,%7}, {%8,%9}, {%0,%1,%2,%3};"
    : "+f"(c[0]), "+f"(c[1]), "+f"(c[2]), "+f"(c[3])
    : "r"(a[0]), "r"(a[1]), "r"(a[2]), "r"(a[3]), "r"(b[0]), "r"(b[1]));
}

// ldmatrix x4: 4 consecutive 8x8 b16 matrices -> r[0..3]
DEV void ldsm4(uint32_t* r, uint32_t addr) {
  asm volatile("ldmatrix.sync.aligned.m8n8.x4.shared.b16 {%0,%1,%2,%3}, [%4];"
               : "=r"(r[0]), "=r"(r[1]), "=r"(r[2]), "=r"(r[3]) : "r"(addr));
}

DEV float elu_f(float x) { return x > 0.f ? x : expm1f(x); }
DEV uint32_t f2h2(float x, float y) {
  __half2 h = __floats2half2_rn(x, y);
  return *reinterpret_cast<uint32_t*>(&h);
}

// Smem rows: 64 k-halves (128 B data) padded to 72 halves (144 B = 9*16 B).
// ldmatrix phase (8 consecutive rows, one 16B seg each): banks 4i..4i+3 -> all
// 32 banks once: conflict-free.
static constexpr int ROWH = 72;                    // halves per padded row
static constexpr int ROWB = 144;                   // bytes per padded row

// QK epilogue staging: 128 rows x 128 cols fp32, rows padded to 136 floats.
static constexpr int EPIW = 136;

// ---------------- prep kernels ----------------
__global__ void f2h_all_kernel(const float* __restrict__ Q,
                               const float* __restrict__ K,
                               const float* __restrict__ V) {
  const int bi = blockIdx.x;            // 0..24575 (8192 blocks per tensor)
  const int which = bi >> 13;
  const int blk = bi & 8191;
  const float* src = (which == 0) ? Q : (which == 1) ? K : V;
  __half* dst = (which == 0) ? g_Qh : (which == 1) ? g_Kh : g_Vh;
  const size_t base = ((size_t)blk * 256 + threadIdx.x) * 8;
  float4 a = *reinterpret_cast<const float4*>(src + base);
  float4 b = *reinterpret_cast<const float4*>(src + base + 4);
  uint4 o;
  o.x = f2h2(a.x, a.y); o.y = f2h2(a.z, a.w);
  o.z = f2h2(b.x, b.y); o.w = f2h2(b.z, b.w);
  *reinterpret_cast<uint4*>(dst + base) = o;
}

__global__ void transpose_qk_kernel(const float* __restrict__ Wq,
                                    const float* __restrict__ Wk) {
  __shared__ float tile[32][33];
  const float* src = (blockIdx.z == 0) ? Wq : Wk;
  __half* dst = (blockIdx.z == 0) ? g_WqT : g_WkT;
  const int c0 = blockIdx.x * 32, r0 = blockIdx.y * 32;
  const int tx = threadIdx.x, ty = threadIdx.y;
  #pragma unroll
  for (int i = 0; i < 32; i += 8)
    tile[ty + i][tx] = src[(size_t)(r0 + ty + i) * Ff + (c0 + tx)];
  __syncthreads();
  #pragma unroll
  for (int i = 0; i < 32; i += 8)
    dst[(size_t)(c0 + ty + i) * Dd + (r0 + tx)] = __float2half_rn(tile[tx][ty + i]);
}

__global__ void transpose_v_kernel(const float* __restrict__ Wv) {
  __shared__ float tile[32][33];
  // fold reduction-buffer zeroing in
  int id = (blockIdx.y * 64 + blockIdx.x) * 256 + threadIdx.y * 32 + threadIdx.x;
  if (id < Bn) { g_sQ[id] = 0.f; g_sK[id] = 0.f; g_qk[id] = 0.f; }
  const int c0 = blockIdx.x * 32, r0 = blockIdx.y * 32;
  const int tx = threadIdx.x, ty = threadIdx.y;
  #pragma unroll
  for (int i = 0; i < 32; i += 8)
    tile[ty + i][tx] = Wv[(size_t)(r0 + ty + i) * Dd + (c0 + tx)];
  __syncthreads();
  #pragma unroll
  for (int i = 0; i < 32; i += 8)
    g_WvT[(size_t)(c0 + ty + i) * Dd + (r0 + tx)] = __float2half_rn(tile[tx][ty + i]);
}

// ---------------- fused Q/K feature kernel ----------------
// ONE 512-thread CTA covers 128 rows x 128 cols for BOTH gemms.
// 16 warps: side = wid>>3 (0 = Q gemm, 1 = K gemm); within a side 2m x 4n of
// 64x32 warp tiles (acc 64 regs). K-chunk 64, 2-stage single-barrier pipeline.
// Stage: A 256 rows (Q 128 | K 128) + B 256 rows (BQ 128 | BK 128) = 73728 B.
static constexpr int QK_STAGE = 512 * ROWB;               // 73728
static constexpr int QK_SMEM  = 2 * QK_STAGE;             // 147456

__global__ void __launch_bounds__(512, 1)
gemm_qk_kernel(const float* __restrict__ bq, const float* __restrict__ bk)
{
  extern __shared__ __align__(128) char smem[];
  const uint32_t sb = smem_u32(smem);
  const int tid = threadIdx.x;
  const int wid = tid >> 5, lane = tid & 31;
  const int g = lane >> 2, tig = lane & 3;
  const int side = wid >> 3;          // 0 = Q gemm, 1 = K gemm
  const int w2 = wid & 7;
  const int wm = w2 >> 2;             // 0..1 (64-row block)
  const int wn = w2 & 3;              // 0..3 (32-col block)
  const int m0 = blockIdx.y * 128;
  const int n0 = blockIdx.x * 128;

  auto load_stage = [&](int it, int s) {
    const int k0 = it * 64;                 // halves
    const uint32_t base = sb + (uint32_t)s * QK_STAGE;
    #pragma unroll
    for (int i = 0; i < 4; ++i) {           // A: 2048 chunks (Q rows 0-127, K 128-255)
      int ch = tid + i * 512;
      int r = ch >> 3, c = ch & 7;
      uint32_t off = (uint32_t)(r * ROWB + c * 16);
      const __half* src = (i < 2) ? (g_Qh + (size_t)(m0 + r) * Dd)
                                  : (g_Kh + (size_t)(m0 + r - 128) * Dd);
      cp16(base + off, src + k0 + c * 8);
    }
    #pragma unroll
    for (int i = 0; i < 4; ++i) {           // B: 2048 chunks (BQ 0-127, BK 128-255)
      int ch = tid + i * 512;
      int r = ch >> 3, c = ch & 7;
      uint32_t off = (uint32_t)(256 * ROWB + r * ROWB + c * 16);
      const __half* src = (i < 2) ? (g_WqT + (size_t)(n0 + r) * Dd)
                                  : (g_WkT + (size_t)(n0 + r - 128) * Dd);
      cp16(base + off, src + k0 + c * 8);
    }
    cp_commit();
  };

  // ldmatrix lane offsets
  const int l15 = lane & 15;
  const uint32_t aLane = (uint32_t)(l15 * ROWB) + ((lane >> 4) * 16);
  uint32_t aoff[4];
  #pragma unroll
  for (int i = 0; i < 4; ++i)
    aoff[i] = (uint32_t)((side * 128 + wm * 64 + i * 16) * ROWB) + aLane;
  const int nbl = ((lane >> 4) & 1) * 8 + (lane & 7);
  const uint32_t bLane = (uint32_t)(nbl * ROWB) + (((lane >> 3) & 1) * 16);
  uint32_t boff[2];
  #pragma unroll
  for (int jp = 0; jp < 2; ++jp)
    boff[jp] = (uint32_t)((256 + side * 128 + wn * 32 + jp * 16) * ROWB) + bLane;

  float cc[4][4][4];
  #pragma unroll
  for (int i = 0; i < 4; ++i)
    #pragma unroll
    for (int j = 0; j < 4; ++j)
      #pragma unroll
      for (int t = 0; t < 4; ++t) cc[i][j][t] = 0.f;

  load_stage(0, 0);

  const int NIT = Dd / 64;   // 32
  for (int it = 0; it < NIT; ++it) {
    cp_wait0();                // load(it) landed
    __syncthreads();           // all warps done reading stage (it-1)&1
    if (it + 1 < NIT) load_stage(it + 1, (it + 1) & 1);

    const uint32_t stA = sb + (uint32_t)(it & 1) * QK_STAGE;
    #pragma unroll
    for (int ks = 0; ks < 4; ++ks) {
      const uint32_t kb = ks * 32;          // 16 halves = 32 bytes
      uint32_t a[4][4];
      ldsm4(a[0], stA + aoff[0] + kb);
      ldsm4(a[1], stA + aoff[1] + kb);
      ldsm4(a[2], stA + aoff[2] + kb);
      ldsm4(a[3], stA + aoff[3] + kb);
      uint32_t b[4][2];
      ldsm4(&b[0][0], stA + boff[0] + kb);
      ldsm4(&b[2][0], stA + boff[1] + kb);
      #pragma unroll
      for (int i = 0; i < 4; ++i)
        #pragma unroll
        for (int j = 0; j < 4; ++j)
          mma16(cc[i][j], a[i], b[j]);
    }
  }

  // ---- epilogue ----
  const float* bias = side ? bk : bq;
  float bb[4][2];
  #pragma unroll
  for (int j = 0; j < 4; ++j) {
    const int col = n0 + wn * 32 + j * 8 + 2 * tig;
    bb[j][0] = bias[col]; bb[j][1] = bias[col + 1];
  }
  // bias + ELU in place; per-row own-side sums
  #pragma unroll
  for (int i = 0; i < 4; ++i) {
    float s0 = 0.f, s1 = 0.f;
    #pragma unroll
    for (int j = 0; j < 4; ++j) {
      cc[i][j][0] = elu_f(cc[i][j][0] + bb[j][0]);
      cc[i][j][1] = elu_f(cc[i][j][1] + bb[j][1]);
      cc[i][j][2] = elu_f(cc[i][j][2] + bb[j][0]);
      cc[i][j][3] = elu_f(cc[i][j][3] + bb[j][1]);
      s0 += cc[i][j][0] + cc[i][j][1];
      s1 += cc[i][j][2] + cc[i][j][3];
    }
    #pragma unroll
    for (int m = 1; m <= 2; m <<= 1) {
      s0 += __shfl_xor_sync(0xffffffffu, s0, m);
      s1 += __shfl_xor_sync(0xffffffffu, s1, m);
    }
    if (tig == 0) {
      float* arr = side ? g_sK : g_sQ;
      const int r = m0 + wm * 64 + i * 16 + g;
      atomicAdd(&arr[r], s0);
      atomicAdd(&arr[r + 8], s1);
    }
  }
  __syncthreads();             // mainloop smem reads done everywhere
  float* epi = reinterpret_cast<float*>(smem);   // 128 x EPIW floats (69.6 KB)
  if (side == 1) {             // K warps stage their ELU'd tile
    #pragma unroll
    for (int i = 0; i < 4; ++i) {
      const int r0 = wm * 64 + i * 16 + g, r1 = r0 + 8;
      #pragma unroll
      for (int j = 0; j < 4; ++j) {
        const int c = wn * 32 + j * 8 + 2 * tig;
        *reinterpret_cast<float2*>(epi + r0 * EPIW + c) = make_float2(cc[i][j][0], cc[i][j][1]);
        *reinterpret_cast<float2*>(epi + r1 * EPIW + c) = make_float2(cc[i][j][2], cc[i][j][3]);
      }
    }
  }
  __syncthreads();
  if (side == 0) {             // Q warps form q*k row-products
    #pragma unroll
    for (int i = 0; i < 4; ++i) {
      const int r0 = wm * 64 + i * 16 + g, r1 = r0 + 8;
      float p0 = 0.f, p1 = 0.f;
      #pragma unroll
      for (int j = 0; j < 4; ++j) {
        const int c = wn * 32 + j * 8 + 2 * tig;
        float2 k0v = *reinterpret_cast<const float2*>(epi + r0 * EPIW + c);
        float2 k1v = *reinterpret_cast<const float2*>(epi + r1 * EPIW + c);
        p0 += cc[i][j][0] * k0v.x + cc[i][j][1] * k0v.y;
        p1 += cc[i][j][2] * k1v.x + cc[i][j][3] * k1v.y;
      }
      #pragma unroll
      for (int m = 1; m <= 2; m <<= 1) {
        p0 += __shfl_xor_sync(0xffffffffu, p0, m);
        p1 += __shfl_xor_sync(0xffffffffu, p1, m);
      }
      if (tig == 0) {
        atomicAdd(&g_qk[m0 + r0], p0);
        atomicAdd(&g_qk[m0 + r1], p1);
      }
    }
  }
}

// ---------------- V projection kernel ----------------
// CTA 128x128, warp tile 64x32, K-chunk 64, 3-stage single-barrier pipeline,
// 2 CTAs/SM. (unchanged from R10)
static constexpr int TILE_B  = 128 * ROWB;                // 18432
static constexpr int V_STAGE = 2 * TILE_B;                // 36864
static constexpr int V_SMEM  = 3 * V_STAGE;               // 110592

__global__ void __launch_bounds__(256, 2)
gemm_v_kernel(const float* __restrict__ bv, float* __restrict__ out)
{
  extern __shared__ __align__(128) char smem[];
  const uint32_t sb = smem_u32(smem);
  const int tid = threadIdx.x;
  const int wid = tid >> 5, lane = tid & 31;
  const int g = lane >> 2, tig = lane & 3;
  const int wm = wid >> 2, wn = wid & 3;
  const int m0 = blockIdx.y * 128;
  const int n0 = blockIdx.x * 128;

  auto load_stage = [&](int it, int s) {
    const int k0 = it * 64;
    const uint32_t base = sb + (uint32_t)s * V_STAGE;
    #pragma unroll
    for (int i = 0; i < 4; ++i) {
      int ch = tid + i * 256;
      int r = ch >> 3, c = ch & 7;
      uint32_t off = (uint32_t)(r * ROWB + c * 16);
      cp16(base + off,          g_Vh  + (size_t)(m0 + r) * Dd + k0 + c * 8);
      cp16(base + TILE_B + off, g_WvT + (size_t)(n0 + r) * Dd + k0 + c * 8);
    }
    cp_commit();
  };

  const int l15 = lane & 15;
  const uint32_t aLane = (uint32_t)(l15 * ROWB) + ((lane >> 4) * 16);
  uint32_t aoff[4];
  #pragma unroll
  for (int i = 0; i < 4; ++i)
    aoff[i] = (uint32_t)((wm * 64 + i * 16) * ROWB) + aLane;
  const int nbl = ((lane >> 4) & 1) * 8 + (lane & 7);
  const uint32_t bLane = (uint32_t)(nbl * ROWB) + (((lane >> 3) & 1) * 16);
  uint32_t boff[2];
  #pragma unroll
  for (int jp = 0; jp < 2; ++jp)
    boff[jp] = (uint32_t)((wn * 32 + jp * 16) * ROWB) + bLane;

  float cc[4][4][4];
  #pragma unroll
  for (int i = 0; i < 4; ++i)
    #pragma unroll
    for (int j = 0; j < 4; ++j)
      #pragma unroll
      for (int t = 0; t < 4; ++t) cc[i][j][t] = 0.f;

  load_stage(0, 0);
  load_stage(1, 1);

  const int NIT = Dd / 64;   // 32
  for (int it = 0; it < NIT; ++it) {
    cp_wait1();                // load(it) landed; load(it+1) may be in flight
    __syncthreads();           // all warps done reading stage (it-1)%3
    if (it + 2 < NIT) load_stage(it + 2, (it + 2) % 3);
    else cp_commit();          // keep group counts uniform for wait1

    const uint32_t stA = sb + (uint32_t)(it % 3) * V_STAGE;
    #pragma unroll
    for (int ks = 0; ks < 4; ++ks) {
      const uint32_t kb = ks * 32;
      uint32_t a[4][4];
      ldsm4(a[0], stA + aoff[0] + kb);
      ldsm4(a[1], stA + aoff[1] + kb);
      ldsm4(a[2], stA + aoff[2] + kb);
      ldsm4(a[3], stA + aoff[3] + kb);
      uint32_t b[4][2];
      ldsm4(&b[0][0], stA + TILE_B + boff[0] + kb);
      ldsm4(&b[2][0], stA + TILE_B + boff[1] + kb);
      #pragma unroll
      for (int i = 0; i < 4; ++i)
        #pragma unroll
        for (int j = 0; j < 4; ++j)
          mma16(cc[i][j], a[i], b[j]);
    }
  }

  // Epilogue: out[r, n] = coef[r] * (acc + bv[n])
  float bvc[4][2];
  #pragma unroll
  for (int j = 0; j < 4; ++j) {
    const int col = n0 + wn * 32 + j * 8 + 2 * tig;
    bvc[j][0] = bv[col]; bvc[j][1] = bv[col + 1];
  }
  #pragma unroll
  for (int i = 0; i < 4; ++i) {
    const int r0 = m0 + wm * 64 + i * 16 + g;
    const int r1 = r0 + 8;
    const float c0 = g_qk[r0] / (g_sQ[r0] * g_sK[r0] + 1e-6f);
    const float c1 = g_qk[r1] / (g_sQ[r1] * g_sK[r1] + 1e-6f);
    #pragma unroll
    for (int j = 0; j < 4; ++j) {
      const int col = n0 + wn * 32 + j * 8 + 2 * tig;
      float2 v0, v1;
      v0.x = c0 * (cc[i][j][0] + bvc[j][0]);
      v0.y = c0 * (cc[i][j][1] + bvc[j][1]);
      v1.x = c1 * (cc[i][j][2] + bvc[j][0]);
      v1.y = c1 * (cc[i][j][3] + bvc[j][1]);
      *reinterpret_cast<float2*>(out + (size_t)r0 * Dd + col) = v0;
      *reinterpret_cast<float2*>(out + (size_t)r1 * Dd + col) = v1;
    }
  }
}

// ---------------- host launcher ----------------
extern "C" void kernel_launch(void* const* d_in, const int* /*in_sizes*/, int /*n_in*/,
                              void* d_out, int /*out_size*/) {
  const float* Q  = (const float*)d_in[0];
  const float* K  = (const float*)d_in[1];
  const float* V  = (const float*)d_in[2];
  const float* Wq = (const float*)d_in[3];
  const float* bq = (const float*)d_in[4];
  const float* Wk = (const float*)d_in[5];
  const float* bk = (const float*)d_in[6];
  const float* Wv = (const float*)d_in[7];
  const float* bv = (const float*)d_in[8];
  float* out = (float*)d_out;

  cudaFuncSetAttribute(gemm_qk_kernel, cudaFuncAttributeMaxDynamicSharedMemorySize, QK_SMEM);
  cudaFuncSetAttribute(gemm_v_kernel,  cudaFuncAttributeMaxDynamicSharedMemorySize, V_SMEM);

  // launch index 3 (the one ncu profiles) = gemm_qk (restructured this round)
  f2h_all_kernel<<<3 * 8192, 256>>>(Q, K, V);                                    // 0
  transpose_qk_kernel<<<dim3(Ff / 32, Dd / 32, 2), dim3(32, 8)>>>(Wq, Wk);       // 1
  transpose_v_kernel <<<dim3(Dd / 32, Dd / 32),    dim3(32, 8)>>>(Wv);           // 2 (+zeroing)
  gemm_qk_kernel<<<dim3(Ff / 128, Bn / 128), 512, QK_SMEM>>>(bq, bk);            // 3
  gemm_v_kernel <<<dim3(Dd / 128, Bn / 128), 256, V_SMEM>>>(bv, out);            // 4
}

// round 12
// speedup vs baseline: 1.0890x; 1.0890x over previous
#include <cuda_runtime.h>
#include <cuda_fp16.h>
#include <cstdint>
#include <cstddef>

#define DEV __device__ __forceinline__

static constexpr int Bn = 8192;   // batch rows
static constexpr int Dd = 2048;   // model dim (K of GEMMs, N of V GEMM)
static constexpr int Ff = 1024;   // feature dim (N of Q/K GEMMs)

// ---------------- scratch (device globals: allocation-free) ----------------
__device__ __half g_Qh [(size_t)Bn * Dd];   // 32 MB
__device__ __half g_Kh [(size_t)Bn * Dd];   // 32 MB
__device__ __half g_Vh [(size_t)Bn * Dd];   // 32 MB
__device__ __half g_WqT[(size_t)Ff * Dd];   // [F][D] 4 MB
__device__ __half g_WkT[(size_t)Ff * Dd];   // [F][D] 4 MB
__device__ __half g_WvT[(size_t)Dd * Dd];   // [D][D] 8 MB
__device__ float g_sQ[Bn];
__device__ float g_sK[Bn];
__device__ float g_qk[Bn];
__device__ int   g_done;                    // QK-block completion counter

// ---------------- helpers ----------------
DEV uint32_t smem_u32(const void* p) {
  uint32_t a;
  asm("{ .reg .u64 t; cvta.to.shared.u64 t, %1; cvt.u32.u64 %0, t; }" : "=r"(a) : "l"(p));
  return a;
}
DEV void cp16(uint32_t dst, const void* src) {
  asm volatile("cp.async.cg.shared.global [%0], [%1], 16;" :: "r"(dst), "l"(src));
}
DEV void cp_commit() { asm volatile("cp.async.commit_group;" ::: "memory"); }
DEV void cp_wait0()  { asm volatile("cp.async.wait_group 0;" ::: "memory"); }
DEV void cp_wait1()  { asm volatile("cp.async.wait_group 1;" ::: "memory"); }

// mma m16n8k16 fp16 (fp32 acc)
DEV void mma16(float c[4], const uint32_t a[4], const uint32_t b[2]) {
  asm volatile(
    "mma.sync.aligned.m16n8k16.row.col.f32.f16.f16.f32 "
    "{%0,%1,%2,%3}, {%4,%5,%6,%7}, {%8,%9}, {%0,%1,%2,%3};"
    : "+f"(c[0]), "+f"(c[1]), "+f"(c[2]), "+f"(c[3])
    : "r"(a[0]), "r"(a[1]), "r"(a[2]), "r"(a[3]), "r"(b[0]), "r"(b[1]));
}

// ldmatrix x4: 4 consecutive 8x8 b16 matrices -> r[0..3]
DEV void ldsm4(uint32_t* r, uint32_t addr) {
  asm volatile("ldmatrix.sync.aligned.m8n8.x4.shared.b16 {%0,%1,%2,%3}, [%4];"
               : "=r"(r[0]), "=r"(r[1]), "=r"(r[2]), "=r"(r[3]) : "r"(addr));
}

DEV float elu_f(float x) { return x > 0.f ? x : expm1f(x); }
DEV uint32_t f2h2(float x, float y) {
  __half2 h = __floats2half2_rn(x, y);
  return *reinterpret_cast<uint32_t*>(&h);
}
DEV float ldcg(const float* p) {
  float v;
  asm volatile("ld.global.cg.f32 %0, [%1];" : "=f"(v) : "l"(p));
  return v;
}

// Smem rows: 64 k-halves (128 B data) padded to 72 halves (144 B = 9*16 B).
// ldmatrix phase (8 consecutive rows, one 16B seg each): banks 4i..4i+3 -> all
// 32 banks once: conflict-free.
static constexpr int ROWH = 72;                    // halves per padded row
static constexpr int ROWB = 144;                   // bytes per padded row

// QK epilogue staging: 64 rows x 128 cols fp32, rows padded to 136 floats.
static constexpr int EPIW = 136;

// ---------------- prep kernels ----------------
__global__ void f2h_all_kernel(const float* __restrict__ Q,
                               const float* __restrict__ K,
                               const float* __restrict__ V) {
  const int bi = blockIdx.x;            // 0..24575 (8192 blocks per tensor)
  const int which = bi >> 13;
  const int blk = bi & 8191;
  const float* src = (which == 0) ? Q : (which == 1) ? K : V;
  __half* dst = (which == 0) ? g_Qh : (which == 1) ? g_Kh : g_Vh;
  const size_t base = ((size_t)blk * 256 + threadIdx.x) * 8;
  float4 a = *reinterpret_cast<const float4*>(src + base);
  float4 b = *reinterpret_cast<const float4*>(src + base + 4);
  uint4 o;
  o.x = f2h2(a.x, a.y); o.y = f2h2(a.z, a.w);
  o.z = f2h2(b.x, b.y); o.w = f2h2(b.z, b.w);
  *reinterpret_cast<uint4*>(dst + base) = o;
}

__global__ void transpose_qk_kernel(const float* __restrict__ Wq,
                                    const float* __restrict__ Wk) {
  __shared__ float tile[32][33];
  const float* src = (blockIdx.z == 0) ? Wq : Wk;
  __half* dst = (blockIdx.z == 0) ? g_WqT : g_WkT;
  const int c0 = blockIdx.x * 32, r0 = blockIdx.y * 32;
  const int tx = threadIdx.x, ty = threadIdx.y;
  #pragma unroll
  for (int i = 0; i < 32; i += 8)
    tile[ty + i][tx] = src[(size_t)(r0 + ty + i) * Ff + (c0 + tx)];
  __syncthreads();
  #pragma unroll
  for (int i = 0; i < 32; i += 8)
    dst[(size_t)(c0 + ty + i) * Dd + (r0 + tx)] = __float2half_rn(tile[tx][ty + i]);
}

__global__ void transpose_v_kernel(const float* __restrict__ Wv) {
  __shared__ float tile[32][33];
  // fold reduction-buffer zeroing + done-counter reset in
  if (blockIdx.x == 0 && blockIdx.y == 0 && threadIdx.x == 0 && threadIdx.y == 0)
    g_done = 0;
  int id = (blockIdx.y * 64 + blockIdx.x) * 256 + threadIdx.y * 32 + threadIdx.x;
  if (id < Bn) { g_sQ[id] = 0.f; g_sK[id] = 0.f; g_qk[id] = 0.f; }
  const int c0 = blockIdx.x * 32, r0 = blockIdx.y * 32;
  const int tx = threadIdx.x, ty = threadIdx.y;
  #pragma unroll
  for (int i = 0; i < 32; i += 8)
    tile[ty + i][tx] = Wv[(size_t)(r0 + ty + i) * Dd + (c0 + tx)];
  __syncthreads();
  #pragma unroll
  for (int i = 0; i < 32; i += 8)
    g_WvT[(size_t)(c0 + ty + i) * Dd + (r0 + tx)] = __float2half_rn(tile[tx][ty + i]);
}

// ---------------- fused GEMM kernel ----------------
// Blocks 0..1023: QK body (R10 proven config) -- CTA 64 rows x 128 cols, warps
//   0-3 Q-gemm / 4-7 K-gemm, 64x32 warp tiles, 2-stage single-barrier pipeline.
// Blocks 1024..2047: V body (R10 proven config) -- CTA 128x128, 64x32 warp
//   tiles, 3-stage single-barrier pipeline.
// V epilogue waits on g_done == 1024 (ordered block dispatch -> no deadlock).
static constexpr int QK_STAGE = (128 + 256) * ROWB;       // 55296
static constexpr int QK_SMEM  = 2 * QK_STAGE;             // 110592
static constexpr int TILE_B   = 128 * ROWB;               // 18432
static constexpr int V_STAGE  = 2 * TILE_B;               // 36864
static constexpr int V_SMEM   = 3 * V_STAGE;              // 110592
static constexpr int G_SMEM   = (QK_SMEM > V_SMEM) ? QK_SMEM : V_SMEM;
static constexpr int QK_BLOCKS = (Ff / 128) * (Bn / 64);  // 1024

__global__ void __launch_bounds__(256, 2)
gemm_fused_kernel(const float* __restrict__ bq, const float* __restrict__ bk,
                  const float* __restrict__ bv, float* __restrict__ out)
{
  extern __shared__ __align__(128) char smem[];
  const uint32_t sb = smem_u32(smem);
  const int tid = threadIdx.x;
  const int wid = tid >> 5, lane = tid & 31;
  const int g = lane >> 2, tig = lane & 3;

  // common ldmatrix lane geometry
  const int l15 = lane & 15;
  const uint32_t aLane = (uint32_t)(l15 * ROWB) + ((lane >> 4) * 16);
  const int nbl = ((lane >> 4) & 1) * 8 + (lane & 7);
  const uint32_t bLane = (uint32_t)(nbl * ROWB) + (((lane >> 3) & 1) * 16);

  if (blockIdx.x < QK_BLOCKS) {
    // ======================= QK body =======================
    const int bid = blockIdx.x;
    const int side = wid >> 2;          // 0 = Q gemm, 1 = K gemm
    const int w = wid & 3;              // 32-col block
    const int m0 = (bid >> 3) * 64;
    const int n0 = (bid & 7) * 128;

    auto load_stage = [&](int it, int s) {
      const int k0 = it * 64;
      const uint32_t base = sb + (uint32_t)s * QK_STAGE;
      #pragma unroll
      for (int i = 0; i < 4; ++i) {         // A: Q rows 0-63, K rows 64-127
        int ch = tid + i * 256;
        int r = ch >> 3, c = ch & 7;
        uint32_t off = (uint32_t)(r * ROWB + c * 16);
        const __half* src = (i < 2) ? (g_Qh + (size_t)(m0 + r) * Dd)
                                    : (g_Kh + (size_t)(m0 + r - 64) * Dd);
        cp16(base + off, src + k0 + c * 8);
      }
      #pragma unroll
      for (int i = 0; i < 8; ++i) {         // B: BQ rows 0-127, BK rows 128-255
        int ch = tid + i * 256;
        int r = ch >> 3, c = ch & 7;
        uint32_t off = (uint32_t)(128 * ROWB + r * ROWB + c * 16);
        const __half* src = (i < 4) ? (g_WqT + (size_t)(n0 + r) * Dd)
                                    : (g_WkT + (size_t)(n0 + r - 128) * Dd);
        cp16(base + off, src + k0 + c * 8);
      }
      cp_commit();
    };

    uint32_t aoff[4];
    #pragma unroll
    for (int i = 0; i < 4; ++i)
      aoff[i] = (uint32_t)((side * 64 + i * 16) * ROWB) + aLane;
    uint32_t boff[2];
    #pragma unroll
    for (int jp = 0; jp < 2; ++jp)
      boff[jp] = (uint32_t)((128 + side * 128 + w * 32 + jp * 16) * ROWB) + bLane;

    float cc[4][4][4];
    #pragma unroll
    for (int i = 0; i < 4; ++i)
      #pragma unroll
      for (int j = 0; j < 4; ++j)
        #pragma unroll
        for (int t = 0; t < 4; ++t) cc[i][j][t] = 0.f;

    load_stage(0, 0);

    const int NIT = Dd / 64;   // 32
    for (int it = 0; it < NIT; ++it) {
      cp_wait0();
      __syncthreads();
      if (it + 1 < NIT) load_stage(it + 1, (it + 1) & 1);

      const uint32_t stA = sb + (uint32_t)(it & 1) * QK_STAGE;
      #pragma unroll
      for (int ks = 0; ks < 4; ++ks) {
        const uint32_t kb = ks * 32;
        uint32_t a[4][4];
        ldsm4(a[0], stA + aoff[0] + kb);
        ldsm4(a[1], stA + aoff[1] + kb);
        ldsm4(a[2], stA + aoff[2] + kb);
        ldsm4(a[3], stA + aoff[3] + kb);
        uint32_t b[4][2];
        ldsm4(&b[0][0], stA + boff[0] + kb);
        ldsm4(&b[2][0], stA + boff[1] + kb);
        #pragma unroll
        for (int i = 0; i < 4; ++i)
          #pragma unroll
          for (int j = 0; j < 4; ++j)
            mma16(cc[i][j], a[i], b[j]);
      }
    }

    // ---- epilogue ----
    const float* bias = side ? bk : bq;
    float bb[4][2];
    #pragma unroll
    for (int j = 0; j < 4; ++j) {
      const int col = n0 + w * 32 + j * 8 + 2 * tig;
      bb[j][0] = bias[col]; bb[j][1] = bias[col + 1];
    }
    #pragma unroll
    for (int i = 0; i < 4; ++i) {
      float s0 = 0.f, s1 = 0.f;
      #pragma unroll
      for (int j = 0; j < 4; ++j) {
        cc[i][j][0] = elu_f(cc[i][j][0] + bb[j][0]);
        cc[i][j][1] = elu_f(cc[i][j][1] + bb[j][1]);
        cc[i][j][2] = elu_f(cc[i][j][2] + bb[j][0]);
        cc[i][j][3] = elu_f(cc[i][j][3] + bb[j][1]);
        s0 += cc[i][j][0] + cc[i][j][1];
        s1 += cc[i][j][2] + cc[i][j][3];
      }
      #pragma unroll
      for (int m = 1; m <= 2; m <<= 1) {
        s0 += __shfl_xor_sync(0xffffffffu, s0, m);
        s1 += __shfl_xor_sync(0xffffffffu, s1, m);
      }
      if (tig == 0) {
        float* arr = side ? g_sK : g_sQ;
        atomicAdd(&arr[m0 + i * 16 + g], s0);
        atomicAdd(&arr[m0 + i * 16 + g + 8], s1);
      }
    }
    __syncthreads();
    float* epi = reinterpret_cast<float*>(smem);   // 64 x EPIW floats
    if (side == 1) {
      #pragma unroll
      for (int i = 0; i < 4; ++i) {
        const int r0 = i * 16 + g, r1 = r0 + 8;
        #pragma unroll
        for (int j = 0; j < 4; ++j) {
          const int c = w * 32 + j * 8 + 2 * tig;
          *reinterpret_cast<float2*>(epi + r0 * EPIW + c) = make_float2(cc[i][j][0], cc[i][j][1]);
          *reinterpret_cast<float2*>(epi + r1 * EPIW + c) = make_float2(cc[i][j][2], cc[i][j][3]);
        }
      }
    }
    __syncthreads();
    if (side == 0) {
      #pragma unroll
      for (int i = 0; i < 4; ++i) {
        const int r0 = i * 16 + g, r1 = r0 + 8;
        float p0 = 0.f, p1 = 0.f;
        #pragma unroll
        for (int j = 0; j < 4; ++j) {
          const int c = w * 32 + j * 8 + 2 * tig;
          float2 k0v = *reinterpret_cast<const float2*>(epi + r0 * EPIW + c);
          float2 k1v = *reinterpret_cast<const float2*>(epi + r1 * EPIW + c);
          p0 += cc[i][j][0] * k0v.x + cc[i][j][1] * k0v.y;
          p1 += cc[i][j][2] * k1v.x + cc[i][j][3] * k1v.y;
        }
        #pragma unroll
        for (int m = 1; m <= 2; m <<= 1) {
          p0 += __shfl_xor_sync(0xffffffffu, p0, m);
          p1 += __shfl_xor_sync(0xffffffffu, p1, m);
        }
        if (tig == 0) {
          atomicAdd(&g_qk[m0 + i * 16 + g], p0);
          atomicAdd(&g_qk[m0 + i * 16 + g + 8], p1);
        }
      }
    }
    // signal completion (device-scope visibility of all atomics above)
    __threadfence();
    __syncthreads();
    if (tid == 0) atomicAdd(&g_done, 1);

  } else {
    // ======================= V body =======================
    const int bid = blockIdx.x - QK_BLOCKS;
    const int wm = wid >> 2, wn = wid & 3;
    const int m0 = (bid >> 4) * 128;
    const int n0 = (bid & 15) * 128;

    auto load_stage = [&](int it, int s) {
      const int k0 = it * 64;
      const uint32_t base = sb + (uint32_t)s * V_STAGE;
      #pragma unroll
      for (int i = 0; i < 4; ++i) {
        int ch = tid + i * 256;
        int r = ch >> 3, c = ch & 7;
        uint32_t off = (uint32_t)(r * ROWB + c * 16);
        cp16(base + off,          g_Vh  + (size_t)(m0 + r) * Dd + k0 + c * 8);
        cp16(base + TILE_B + off, g_WvT + (size_t)(n0 + r) * Dd + k0 + c * 8);
      }
      cp_commit();
    };

    uint32_t aoff[4];
    #pragma unroll
    for (int i = 0; i < 4; ++i)
      aoff[i] = (uint32_t)((wm * 64 + i * 16) * ROWB) + aLane;
    uint32_t boff[2];
    #pragma unroll
    for (int jp = 0; jp < 2; ++jp)
      boff[jp] = (uint32_t)((wn * 32 + jp * 16) * ROWB) + bLane;

    float cc[4][4][4];
    #pragma unroll
    for (int i = 0; i < 4; ++i)
      #pragma unroll
      for (int j = 0; j < 4; ++j)
        #pragma unroll
        for (int t = 0; t < 4; ++t) cc[i][j][t] = 0.f;

    load_stage(0, 0);
    load_stage(1, 1);

    const int NIT = Dd / 64;   // 32
    for (int it = 0; it < NIT; ++it) {
      cp_wait1();
      __syncthreads();
      if (it + 2 < NIT) load_stage(it + 2, (it + 2) % 3);
      else cp_commit();

      const uint32_t stA = sb + (uint32_t)(it % 3) * V_STAGE;
      #pragma unroll
      for (int ks = 0; ks < 4; ++ks) {
        const uint32_t kb = ks * 32;
        uint32_t a[4][4];
        ldsm4(a[0], stA + aoff[0] + kb);
        ldsm4(a[1], stA + aoff[1] + kb);
        ldsm4(a[2], stA + aoff[2] + kb);
        ldsm4(a[3], stA + aoff[3] + kb);
        uint32_t b[4][2];
        ldsm4(&b[0][0], stA + TILE_B + boff[0] + kb);
        ldsm4(&b[2][0], stA + TILE_B + boff[1] + kb);
        #pragma unroll
        for (int i = 0; i < 4; ++i)
          #pragma unroll
          for (int j = 0; j < 4; ++j)
            mma16(cc[i][j], a[i], b[j]);
      }
    }

    // ---- wait for all QK blocks (ordered dispatch -> no deadlock) ----
    if (tid == 0) {
      int d;
      do {
        asm volatile("ld.global.cg.b32 %0, [%1];" : "=r"(d) : "l"(&g_done));
        if (d < QK_BLOCKS) asm volatile("nanosleep.u32 128;");
      } while (d < QK_BLOCKS);
    }
    __syncthreads();
    __threadfence();

    // Epilogue: out[r, n] = coef[r] * (acc + bv[n])
    float bvc[4][2];
    #pragma unroll
    for (int j = 0; j < 4; ++j) {
      const int col = n0 + wn * 32 + j * 8 + 2 * tig;
      bvc[j][0] = bv[col]; bvc[j][1] = bv[col + 1];
    }
    #pragma unroll
    for (int i = 0; i < 4; ++i) {
      const int r0 = m0 + wm * 64 + i * 16 + g;
      const int r1 = r0 + 8;
      const float c0 = ldcg(&g_qk[r0]) / (ldcg(&g_sQ[r0]) * ldcg(&g_sK[r0]) + 1e-6f);
      const float c1 = ldcg(&g_qk[r1]) / (ldcg(&g_sQ[r1]) * ldcg(&g_sK[r1]) + 1e-6f);
      #pragma unroll
      for (int j = 0; j < 4; ++j) {
        const int col = n0 + wn * 32 + j * 8 + 2 * tig;
        float2 v0, v1;
        v0.x = c0 * (cc[i][j][0] + bvc[j][0]);
        v0.y = c0 * (cc[i][j][1] + bvc[j][1]);
        v1.x = c1 * (cc[i][j][2] + bvc[j][0]);
        v1.y = c1 * (cc[i][j][3] + bvc[j][1]);
        *reinterpret_cast<float2*>(out + (size_t)r0 * Dd + col) = v0;
        *reinterpret_cast<float2*>(out + (size_t)r1 * Dd + col) = v1;
      }
    }
  }
}

// ---------------- host launcher ----------------
extern "C" void kernel_launch(void* const* d_in, const int* /*in_sizes*/, int /*n_in*/,
                              void* d_out, int /*out_size*/) {
  const float* Q  = (const float*)d_in[0];
  const float* K  = (const float*)d_in[1];
  const float* V  = (const float*)d_in[2];
  const float* Wq = (const float*)d_in[3];
  const float* bq = (const float*)d_in[4];
  const float* Wk = (const float*)d_in[5];
  const float* bk = (const float*)d_in[6];
  const float* Wv = (const float*)d_in[7];
  const float* bv = (const float*)d_in[8];
  float* out = (float*)d_out;

  cudaFuncSetAttribute(gemm_fused_kernel, cudaFuncAttributeMaxDynamicSharedMemorySize, G_SMEM);

  const int v_blocks = (Dd / 128) * (Bn / 128);   // 1024
  // launch index 3 (the one ncu profiles) = fused GEMM
  f2h_all_kernel<<<3 * 8192, 256>>>(Q, K, V);                                    // 0
  transpose_qk_kernel<<<dim3(Ff / 32, Dd / 32, 2), dim3(32, 8)>>>(Wq, Wk);       // 1
  transpose_v_kernel <<<dim3(Dd / 32, Dd / 32),    dim3(32, 8)>>>(Wv);           // 2 (+zero/done)
  gemm_fused_kernel<<<QK_BLOCKS + v_blocks, 256, G_SMEM>>>(bq, bk, bv, out);     // 3
}